// round 5
// baseline (speedup 1.0000x reference)
#include <cuda_runtime.h>
#include <math.h>

#define BATCH 4096
#define NROWS 8192
#define DIM   128
#define INV_T 2.0f      // 1 / 0.5

#define BM 128
#define BN 128
#define NSPLIT 16
#define TILES_PER_CTA 4   // 8192 / 128 / 16

// scratch (device globals: allocation-free)
__device__ float g_z [NROWS * DIM];   // normalized rows, row-major
__device__ float g_zT[DIM * NROWS];   // transposed normalized rows
__device__ float g_pos[BATCH];        // z_i[b] . z_j[b]
__device__ float g_denom[NROWS];      // sum_{c != r} exp(sim/T)

// ---------- packed f32x2 helpers ----------
__device__ __forceinline__ unsigned long long pack2(float lo, float hi) {
    unsigned long long r;
    asm("mov.b64 %0, {%1, %2};" : "=l"(r) : "f"(lo), "f"(hi));
    return r;
}
__device__ __forceinline__ void unpack2(unsigned long long v, float &lo, float &hi) {
    asm("mov.b64 {%0, %1}, %2;" : "=f"(lo), "=f"(hi) : "l"(v));
}
__device__ __forceinline__ void fma2(unsigned long long &d,
                                     unsigned long long a,
                                     unsigned long long b) {
    asm("fma.rn.f32x2 %0, %1, %2, %0;" : "+l"(d) : "l"(a), "l"(b));
}

// ---------- zero the denominator accumulator ----------
__global__ void k_init() {
    int i = blockIdx.x * blockDim.x + threadIdx.x;
    if (i < NROWS) g_denom[i] = 0.0f;
}

// ---------- normalize rows, write z and zT ----------
__global__ void k_norm(const float* __restrict__ ei, const float* __restrict__ ej) {
    int w    = (blockIdx.x * blockDim.x + threadIdx.x) >> 5;
    int lane = threadIdx.x & 31;
    if (w >= NROWS) return;
    const float* src = (w < BATCH) ? (ei + (size_t)w * DIM)
                                   : (ej + (size_t)(w - BATCH) * DIM);
    float4 v = ((const float4*)src)[lane];
    float ss = v.x*v.x + v.y*v.y + v.z*v.z + v.w*v.w;
    #pragma unroll
    for (int o = 16; o; o >>= 1) ss += __shfl_xor_sync(0xffffffffu, ss, o);
    float nrm = sqrtf(ss);
    float s   = 1.0f / fmaxf(nrm, 1e-12f);
    v.x *= s; v.y *= s; v.z *= s; v.w *= s;
    ((float4*)(g_z + (size_t)w * DIM))[lane] = v;
    int k0 = lane * 4;
    g_zT[(size_t)(k0 + 0) * NROWS + w] = v.x;
    g_zT[(size_t)(k0 + 1) * NROWS + w] = v.y;
    g_zT[(size_t)(k0 + 2) * NROWS + w] = v.z;
    g_zT[(size_t)(k0 + 3) * NROWS + w] = v.w;
}

// ---------- positives: z_i[b] . z_j[b] ----------
__global__ void k_pos() {
    int w    = (blockIdx.x * blockDim.x + threadIdx.x) >> 5;
    int lane = threadIdx.x & 31;
    if (w >= BATCH) return;
    float4 a = ((const float4*)(g_z + (size_t)w * DIM))[lane];
    float4 b = ((const float4*)(g_z + (size_t)(w + BATCH) * DIM))[lane];
    float d = a.x*b.x + a.y*b.y + a.z*b.z + a.w*b.w;
    #pragma unroll
    for (int o = 16; o; o >>= 1) d += __shfl_xor_sync(0xffffffffu, d, o);
    if (lane == 0) g_pos[w] = d;
}

// ---------- main: sim tile GEMM + fused exp-rowsum ----------
__global__ void __launch_bounds__(256, 1) k_main() {
    extern __shared__ float smem[];
    float* As = smem;              // [DIM][BM]  (k-major)
    float* Bs = smem + DIM * BM;   // [DIM][BN]  (k-major)

    const int tid = threadIdx.x;
    const int tx  = tid & 15;      // col group (8 cols)
    const int ty  = tid >> 4;      // row group (8 rows)
    const int rowStart = blockIdx.x * BM;

    // Load A tile once: As[k][m] = zT[k][rowStart + m] (coalesced, conflict-free)
    #pragma unroll
    for (int it = 0; it < 16; ++it) {
        int f  = tid + it * 256;            // [0, 4096)
        int k  = f >> 5;
        int m4 = (f & 31) * 4;
        *(float4*)&As[k * BM + m4] =
            *(const float4*)&g_zT[(size_t)k * NROWS + rowStart + m4];
    }

    float dsum[8];
    #pragma unroll
    for (int i = 0; i < 8; i++) dsum[i] = 0.0f;

    for (int t = 0; t < TILES_PER_CTA; ++t) {
        const int colStart = (blockIdx.y * TILES_PER_CTA + t) * BN;
        __syncthreads();
        #pragma unroll
        for (int it = 0; it < 16; ++it) {
            int f  = tid + it * 256;
            int k  = f >> 5;
            int n4 = (f & 31) * 4;
            *(float4*)&Bs[k * BN + n4] =
                *(const float4*)&g_zT[(size_t)k * NROWS + colStart + n4];
        }
        __syncthreads();

        unsigned long long acc[8][4];
        #pragma unroll
        for (int i = 0; i < 8; i++)
            #pragma unroll
            for (int j = 0; j < 4; j++) acc[i][j] = 0ULL;

        #pragma unroll 4
        for (int k = 0; k < DIM; ++k) {
            float4 a0 = *(const float4*)&As[k * BM + ty * 8];
            float4 a1 = *(const float4*)&As[k * BM + ty * 8 + 4];
            float4 b0 = *(const float4*)&Bs[k * BN + tx * 8];
            float4 b1 = *(const float4*)&Bs[k * BN + tx * 8 + 4];
            unsigned long long bp0 = pack2(b0.x, b0.y);
            unsigned long long bp1 = pack2(b0.z, b0.w);
            unsigned long long bp2 = pack2(b1.x, b1.y);
            unsigned long long bp3 = pack2(b1.z, b1.w);
            float av[8] = {a0.x, a0.y, a0.z, a0.w, a1.x, a1.y, a1.z, a1.w};
            #pragma unroll
            for (int i = 0; i < 8; i++) {
                unsigned long long ap = pack2(av[i], av[i]);
                fma2(acc[i][0], ap, bp0);
                fma2(acc[i][1], ap, bp1);
                fma2(acc[i][2], ap, bp2);
                fma2(acc[i][3], ap, bp3);
            }
        }

        // exp-accumulate into per-row partial denominators (skip diagonal)
        #pragma unroll
        for (int i = 0; i < 8; i++) {
            int r = rowStart + ty * 8 + i;
            #pragma unroll
            for (int j = 0; j < 4; j++) {
                float lo, hi;
                unpack2(acc[i][j], lo, hi);
                int c = colStart + tx * 8 + j * 2;
                if (r != c)     dsum[i] += __expf(lo * INV_T);
                if (r != c + 1) dsum[i] += __expf(hi * INV_T);
            }
        }
    }

    // reduce dsum across the 16 tx groups, then one atomicAdd per row
    __syncthreads();
    float* red = smem;   // [BM][17] (padded)
    #pragma unroll
    for (int i = 0; i < 8; i++) red[(ty * 8 + i) * 17 + tx] = dsum[i];
    __syncthreads();
    if (tid < BM) {
        float s = 0.0f;
        #pragma unroll
        for (int x = 0; x < 16; x++) s += red[tid * 17 + x];
        atomicAdd(&g_denom[rowStart + tid], s);
    }
}

// ---------- final loss reduction ----------
__global__ void k_loss(float* __restrict__ out) {
    int tid = threadIdx.x;
    float s = 0.0f;
    for (int r = tid; r < NROWS; r += 256) {
        float p = g_pos[(r < BATCH) ? r : (r - BATCH)];
        s += logf(g_denom[r]) - p * INV_T;   // -(pos/T - log denom)
    }
    __shared__ float red[256];
    red[tid] = s;
    __syncthreads();
    #pragma unroll
    for (int st = 128; st; st >>= 1) {
        if (tid < st) red[tid] += red[tid + st];
        __syncthreads();
    }
    if (tid == 0) out[0] = red[0] / (float)NROWS;
}

extern "C" void kernel_launch(void* const* d_in, const int* in_sizes, int n_in,
                              void* d_out, int out_size) {
    const float* emb_i = (const float*)d_in[0];
    const float* emb_j = (const float*)d_in[1];
    float* out = (float*)d_out;

    (void)in_sizes; (void)n_in; (void)out_size;

    cudaFuncSetAttribute(k_main, cudaFuncAttributeMaxDynamicSharedMemorySize,
                         2 * DIM * BM * (int)sizeof(float));

    k_init<<<(NROWS + 255) / 256, 256>>>();
    k_norm<<<NROWS / 8, 256>>>(emb_i, emb_j);
    k_pos<<<BATCH / 8, 256>>>();
    dim3 grid(NROWS / BM, NSPLIT);
    k_main<<<grid, 256, 2 * DIM * BM * (int)sizeof(float)>>>();
    k_loss<<<1, 256>>>(out);
}

// round 8
// speedup vs baseline: 2.8574x; 2.8574x over previous
#include <cuda_runtime.h>
#include <cuda_bf16.h>
#include <stdint.h>
#include <math.h>

#define BATCH 4096
#define NROWS 8192
#define DIM   128
#define INV_T 2.0f            // 1 / 0.5

#define BM 128
#define BN 128
#define NSPLIT 16
#define TILES_PER_CTA 4       // 8192 / 128 / 16  (col tiles per CTA)

#define PADF 136              // floats per smem tile row (bank-stagger 8)
#define PAD2 68               // float2 per row
#define ROWB (PADF * 4)       // 544 bytes
#define TILE_SMEM (BM * ROWB) // 69632 bytes per tile buffer

// ---------------- device scratch (allocation-free) ----------------
__device__ float g_z[NROWS * DIM];                    // normalized fp32 (k_pos)
__device__ __align__(16) float g_zt[NROWS * DIM];     // tf32-rounded, (k,k+4)-interleaved
__device__ float g_pos[BATCH];
__device__ float g_denom[NROWS];

// ---------------- helpers ----------------
__device__ __forceinline__ uint32_t sptr(const void* p) {
    uint32_t a;
    asm("{ .reg .u64 t; cvta.to.shared.u64 t, %1; cvt.u32.u64 %0, t; }"
        : "=r"(a) : "l"(p));
    return a;
}
__device__ __forceinline__ unsigned long long pack2(float lo, float hi) {
    unsigned long long r;
    asm("mov.b64 %0, {%1, %2};" : "=l"(r) : "f"(lo), "f"(hi));
    return r;
}
__device__ __forceinline__ void unpack2(unsigned long long v, float &lo, float &hi) {
    asm("mov.b64 {%0, %1}, %2;" : "=f"(lo), "=f"(hi) : "l"(v));
}
__device__ __forceinline__ unsigned long long fma2n(unsigned long long a,
                                                    unsigned long long b,
                                                    unsigned long long c) {
    unsigned long long d;
    asm("fma.rn.f32x2 %0, %1, %2, %3;" : "=l"(d) : "l"(a), "l"(b), "l"(c));
    return d;
}
__device__ __forceinline__ unsigned long long mul2(unsigned long long a,
                                                   unsigned long long b) {
    unsigned long long d;
    asm("mul.rn.f32x2 %0, %1, %2;" : "=l"(d) : "l"(a), "l"(b));
    return d;
}
__device__ __forceinline__ unsigned long long add2(unsigned long long a,
                                                   unsigned long long b) {
    unsigned long long d;
    asm("add.rn.f32x2 %0, %1, %2;" : "=l"(d) : "l"(a), "l"(b));
    return d;
}
__device__ __forceinline__ uint32_t to_tf32(float f) {
    uint32_t r;
    asm("cvt.rna.tf32.f32 %0, %1;" : "=r"(r) : "f"(f));
    return r;
}

// mma.sync m16n8k8 tf32: c += a * b
__device__ __forceinline__ void mma_tf32(float* c, float2 ag, float2 ag8, float2 b) {
    uint32_t a0 = __float_as_uint(ag.x),  a1 = __float_as_uint(ag8.x);
    uint32_t a2 = __float_as_uint(ag.y),  a3 = __float_as_uint(ag8.y);
    uint32_t b0 = __float_as_uint(b.x),   b1 = __float_as_uint(b.y);
    asm volatile(
        "mma.sync.aligned.m16n8k8.row.col.f32.tf32.tf32.f32 "
        "{%0,%1,%2,%3}, {%4,%5,%6,%7}, {%8,%9}, {%0,%1,%2,%3};"
        : "+f"(c[0]), "+f"(c[1]), "+f"(c[2]), "+f"(c[3])
        : "r"(a0), "r"(a1), "r"(a2), "r"(a3), "r"(b0), "r"(b1));
}

#define CP_ASYNC16(dst_u32, src_ptr) \
    asm volatile("cp.async.cg.shared.global [%0], [%1], 16;" \
                 :: "r"(dst_u32), "l"(src_ptr) : "memory")
#define CP_COMMIT() asm volatile("cp.async.commit_group;" ::: "memory")
#define CP_WAIT0()  asm volatile("cp.async.wait_group 0;" ::: "memory")

// stage a 128x128 float tile (pair-interleaved layout preserved) into padded smem
__device__ __forceinline__ void stage_tile(char* dst, const float* src, int tid) {
    #pragma unroll
    for (int it = 0; it < 16; ++it) {
        int i   = tid + it * 256;         // 4096 16B chunks
        int row = i >> 5;
        int cs  = i & 31;
        uint32_t d = sptr(dst + row * ROWB + cs * 16);
        const char* s = (const char*)(src + (size_t)row * DIM) + cs * 16;
        CP_ASYNC16(d, s);
    }
}

// ---------------- kernels ----------------
__global__ void k_init() {
    int i = blockIdx.x * blockDim.x + threadIdx.x;
    if (i < NROWS) g_denom[i] = 0.0f;
}

__global__ void k_norm(const float* __restrict__ ei, const float* __restrict__ ej) {
    int w    = (blockIdx.x * blockDim.x + threadIdx.x) >> 5;
    int lane = threadIdx.x & 31;
    if (w >= NROWS) return;
    const float* src = (w < BATCH) ? (ei + (size_t)w * DIM)
                                   : (ej + (size_t)(w - BATCH) * DIM);
    float4 v = ((const float4*)src)[lane];
    float ss = v.x*v.x + v.y*v.y + v.z*v.z + v.w*v.w;
    #pragma unroll
    for (int o = 16; o; o >>= 1) ss += __shfl_xor_sync(0xffffffffu, ss, o);
    float s = 1.0f / fmaxf(sqrtf(ss), 1e-12f);
    v.x *= s; v.y *= s; v.z *= s; v.w *= s;
    ((float4*)(g_z + (size_t)w * DIM))[lane] = v;

    // tf32-round + (k, k+4) pair-interleave within each 8-block:
    // k = 8b + p  ->  slot = 8b + (p&3)*2 + (p>>2)
    float vv[4] = { v.x, v.y, v.z, v.w };
    #pragma unroll
    for (int c = 0; c < 4; ++c) {
        int k = lane * 4 + c;
        int b = k >> 3, p = k & 7;
        int slot = b * 8 + (p & 3) * 2 + (p >> 2);
        g_zt[(size_t)w * DIM + slot] = __uint_as_float(to_tf32(vv[c]));
    }
}

__global__ void k_pos() {
    int w    = (blockIdx.x * blockDim.x + threadIdx.x) >> 5;
    int lane = threadIdx.x & 31;
    if (w >= BATCH) return;
    float4 a = ((const float4*)(g_z + (size_t)w * DIM))[lane];
    float4 b = ((const float4*)(g_z + (size_t)(w + BATCH) * DIM))[lane];
    float d = a.x*b.x + a.y*b.y + a.z*b.z + a.w*b.w;
    #pragma unroll
    for (int o = 16; o; o >>= 1) d += __shfl_xor_sync(0xffffffffu, d, o);
    if (lane == 0) g_pos[w] = d;
}

// ---------------- main: tf32 mma.sync GEMM + fused poly-exp epilogue ----------------
__global__ void __launch_bounds__(256, 1) k_main() {
    extern __shared__ char smem[];
    char* AsB     = smem;
    char* BsB[2]  = { smem + TILE_SMEM, smem + 2 * TILE_SMEM };

    const int tid  = threadIdx.x;
    const int wid  = tid >> 5;
    const int lane = tid & 31;
    const int g    = lane >> 2;         // 0..7
    const int q    = lane & 3;          // 0..3
    const int wm   = wid >> 2;          // 0..1  (M warp)
    const int wn   = wid & 3;           // 0..3  (N warp)
    const int rowStart = blockIdx.x * BM;
    const int colBase  = blockIdx.y * (TILES_PER_CTA * BN);

    // prologue: stage A tile + B tile 0
    stage_tile(AsB,    g_zt + (size_t)rowStart * DIM, tid);
    stage_tile(BsB[0], g_zt + (size_t)colBase  * DIM, tid);
    CP_COMMIT();
    CP_WAIT0();
    __syncthreads();

    const float2* As2 = (const float2*)AsB;

    // packed poly constants
    const unsigned long long C720 = pack2(1.f/720.f, 1.f/720.f);
    const unsigned long long C120 = pack2(1.f/120.f, 1.f/120.f);
    const unsigned long long C24  = pack2(1.f/24.f,  1.f/24.f);
    const unsigned long long C6   = pack2(1.f/6.f,   1.f/6.f);
    const unsigned long long CH   = pack2(0.5f, 0.5f);
    const unsigned long long C1   = pack2(1.0f, 1.0f);

    float c[4][4][4];
    #pragma unroll
    for (int i = 0; i < 4; i++)
        #pragma unroll
        for (int j = 0; j < 4; j++)
            #pragma unroll
            for (int e = 0; e < 4; e++) c[i][j][e] = 0.0f;

    unsigned long long rs2[4][2];
    #pragma unroll
    for (int i = 0; i < 4; i++) { rs2[i][0] = 0ULL; rs2[i][1] = 0ULL; }

    for (int t = 0; t < TILES_PER_CTA; ++t) {
        // prefetch next B tile
        if (t + 1 < TILES_PER_CTA) {
            stage_tile(BsB[(t + 1) & 1],
                       g_zt + (size_t)(colBase + (t + 1) * BN) * DIM, tid);
        }
        CP_COMMIT();

        const float2* Bs2 = (const float2*)BsB[t & 1];

        #pragma unroll
        for (int ks = 0; ks < 16; ++ks) {
            float2 a0[4], a1[4], bb[4];
            #pragma unroll
            for (int i = 0; i < 4; i++) {
                int r0 = wm * 64 + i * 16 + g;
                a0[i] = As2[r0 * PAD2 + ks * 4 + q];
                a1[i] = As2[(r0 + 8) * PAD2 + ks * 4 + q];
            }
            #pragma unroll
            for (int j = 0; j < 4; j++) {
                int n0 = wn * 32 + j * 8 + g;
                bb[j] = Bs2[n0 * PAD2 + ks * 4 + q];
            }
            #pragma unroll
            for (int i = 0; i < 4; i++)
                #pragma unroll
                for (int j = 0; j < 4; j++)
                    mma_tf32(c[i][j], a0[i], a1[i], bb[j]);
        }

        // fused exp epilogue on register-resident C, then reset C
        #pragma unroll
        for (int i = 0; i < 4; i++) {
            #pragma unroll
            for (int j = 0; j < 4; j++) {
                #pragma unroll
                for (int h = 0; h < 2; h++) {
                    unsigned long long sp = pack2(c[i][j][2*h], c[i][j][2*h + 1]);
                    unsigned long long y = mul2(sp, CH);          // y = s/2
                    unsigned long long p = fma2n(C720, y, C120);
                    p = fma2n(p, y, C24);
                    p = fma2n(p, y, C6);
                    p = fma2n(p, y, CH);
                    p = fma2n(p, y, C1);
                    p = fma2n(p, y, C1);
                    p = mul2(p, p);                               // exp(s)
                    p = mul2(p, p);                               // exp(2s)
                    rs2[i][h] = add2(rs2[i][h], p);
                    c[i][j][2*h] = 0.0f; c[i][j][2*h + 1] = 0.0f;
                }
            }
        }

        CP_WAIT0();
        __syncthreads();
    }

    // reduce: quad lanes (same g, q=0..3) hold different columns of the same rows
    float* red = (float*)smem;   // [128][4]
    #pragma unroll
    for (int i = 0; i < 4; i++) {
        #pragma unroll
        for (int h = 0; h < 2; h++) {
            float lo, hi;
            unpack2(rs2[i][h], lo, hi);
            float v = lo + hi;
            v += __shfl_xor_sync(0xffffffffu, v, 1);
            v += __shfl_xor_sync(0xffffffffu, v, 2);
            if (q == 0) {
                int row = wm * 64 + i * 16 + h * 8 + g;
                red[row * 4 + wn] = v;
            }
        }
    }
    __syncthreads();
    if (tid < BM) {
        float s = red[tid * 4] + red[tid * 4 + 1] + red[tid * 4 + 2] + red[tid * 4 + 3];
        int r = rowStart + tid;
        // remove diagonal term (present in exactly one col-group): exp(2*sim_rr) ~ e^2
        if ((r >> 9) == (int)blockIdx.y) s -= 7.3890560989306495f;
        atomicAdd(&g_denom[r], s);
    }
}

// ---------------- final loss reduction ----------------
__global__ void k_loss(float* __restrict__ out) {
    int tid = threadIdx.x;
    float s = 0.0f;
    for (int r = tid; r < NROWS; r += 256) {
        float p = g_pos[(r < BATCH) ? r : (r - BATCH)];
        s += logf(g_denom[r]) - p * INV_T;
    }
    __shared__ float red[256];
    red[tid] = s;
    __syncthreads();
    #pragma unroll
    for (int st = 128; st; st >>= 1) {
        if (tid < st) red[tid] += red[tid + st];
        __syncthreads();
    }
    if (tid == 0) out[0] = red[0] / (float)NROWS;
}

extern "C" void kernel_launch(void* const* d_in, const int* in_sizes, int n_in,
                              void* d_out, int out_size) {
    const float* emb_i = (const float*)d_in[0];
    const float* emb_j = (const float*)d_in[1];
    float* out = (float*)d_out;
    (void)in_sizes; (void)n_in; (void)out_size;

    cudaFuncSetAttribute(k_main, cudaFuncAttributeMaxDynamicSharedMemorySize,
                         3 * TILE_SMEM);

    k_init<<<(NROWS + 255) / 256, 256>>>();
    k_norm<<<NROWS / 8, 256>>>(emb_i, emb_j);
    k_pos<<<BATCH / 8, 256>>>();
    dim3 grid(NROWS / BM, NSPLIT);
    k_main<<<grid, 256, 3 * TILE_SMEM>>>();
    k_loss<<<1, 256>>>(out);
}